// round 17
// baseline (speedup 1.0000x reference)
#include <cuda_runtime.h>

// Shapes (fixed): B=1024, n=C*H*W=3072, c=10, m=9
#define NN 3072
#define CC 10
#define MM 9
#define BS 2
#define MAX_B 8192
#define WT_BLKS 30
#define GRAM_BLKS 55
#define AUX_BLKS (WT_BLKS + GRAM_BLKS)   // 85

#define EPS2_INV 100.0f
#define NSTAB 1e-4f
#define SCALE 0.999f          // 1 - c*NUM_STAB

__device__ float g_Wt[CC * NN];       // W transposed [c][n]
__device__ float g_M[CC * CC];        // W^T W
__device__ float g_reg[MAX_B];
__device__ unsigned int g_wt_cnt = 0;     // transpose blocks done
__device__ unsigned int g_gram_cnt = 0;   // gram blocks done
__device__ unsigned int g_fin_cnt = 0;    // main blocks done

// ---------------------------------------------------------------------------
// Single kernel. bid 0..29: transpose. bid 30..84: Gram. bid >=85: main.
// Spinners (main) only wait on lower-bid blocks => launch-order-safe.
__global__ __launch_bounds__(256, 4) void isometry_all(
    const float* __restrict__ data, const float* __restrict__ W,
    const float* __restrict__ bvec, float* __restrict__ out,
    int out_size, int B, int mainBlocks) {
    const int bid = blockIdx.x;
    const int t = threadIdx.x;
    const int warp = t >> 5, lane = t & 31;

    // ================= transpose blocks =================
    if (bid < WT_BLKS) {
        int base = bid * 1024;
        #pragma unroll
        for (int k = 0; k < 4; k++) {
            int idx = base + t + k * 256;
            int j = idx / CC, l = idx - j * CC;
            g_Wt[l * NN + j] = W[idx];
        }
        __threadfence();
        __syncthreads();
        if (t == 0) atomicAdd(&g_wt_cnt, 1u);
        return;
    }

    // ================= gram blocks =================
    if (bid < AUX_BLKS) {
        int pair = bid - WT_BLKS;
        int l = 0, idx = pair;
        #pragma unroll
        for (int q = 0; q < CC; q++)
            if (idx >= CC - q && l == q) { idx -= CC - q; l = q + 1; }
        int lp = l + idx;

        float s = 0.f;
        for (int j = t; j < NN; j += 256)
            s = fmaf(W[j * CC + l], W[j * CC + lp], s);
        #pragma unroll
        for (int o = 16; o; o >>= 1) s += __shfl_xor_sync(0xffffffffu, s, o);
        __shared__ float red0[8];
        if ((t & 31) == 0) red0[t >> 5] = s;
        __syncthreads();
        if (t == 0) {
            float tot = 0.f;
            #pragma unroll
            for (int w = 0; w < 8; w++) tot += red0[w];
            g_M[l * CC + lp] = tot;
            g_M[lp * CC + l] = tot;
            __threadfence();
            atomicAdd(&g_gram_cnt, 1u);
        }
        return;
    }

    // ================= main blocks (R16 path, unchanged) =================
    const int b0 = (bid - AUX_BLKS) * BS;
    const float4* x4 = (const float4*)(data + (size_t)b0 * NN);
    const float4* w4 = (const float4*)g_Wt;

    // prefetch ALL x for this block's 2 samples first: the DRAM-critical
    // stream starts before we wait on the (fast) transpose blocks.
    float4 xv[BS][3];
    #pragma unroll
    for (int s = 0; s < BS; s++)
        #pragma unroll
        for (int it = 0; it < 3; it++)
            xv[s][it] = x4[s * (NN / 4) + it * 256 + t];

    // wait for transpose completion (bounded: lower-bid blocks run first)
    if (t == 0) {
        volatile unsigned int* p = &g_wt_cnt;
        while (*p < WT_BLKS) { __nanosleep(32); }
    }
    __syncthreads();
    __threadfence();   // acquire g_Wt writes

    float acc[BS * CC];
    #pragma unroll
    for (int i = 0; i < BS * CC; i++) acc[i] = 0.f;

    #pragma unroll
    for (int it = 0; it < 3; it++) {
        const int j4 = t + it * 256;
        #pragma unroll
        for (int l = 0; l < CC; l++) {
            float4 wv = w4[l * (NN / 4) + j4];
            #pragma unroll
            for (int s = 0; s < BS; s++) {
                float v = acc[s * CC + l];
                v = fmaf(xv[s][it].x, wv.x, v);
                v = fmaf(xv[s][it].y, wv.y, v);
                v = fmaf(xv[s][it].z, wv.z, v);
                v = fmaf(xv[s][it].w, wv.w, v);
                acc[s * CC + l] = v;
            }
        }
    }

    // --- warp reduce 20 values: split-exchange + butterfly ---
    {
        const bool hi = (lane & 16) != 0;
        #pragma unroll
        for (int i = 0; i < 10; i++) {
            float send = hi ? acc[i] : acc[i + 10];
            float r = __shfl_xor_sync(0xffffffffu, send, 16);
            acc[i] = (hi ? acc[i + 10] : acc[i]) + r;
        }
    }
    #pragma unroll
    for (int off = 8; off; off >>= 1)
        #pragma unroll
        for (int i = 0; i < 10; i++)
            acc[i] += __shfl_xor_sync(0xffffffffu, acc[i], off);

    __shared__ float red[8][BS * CC];
    if ((lane & 15) == 0) {
        int vb = (lane & 16) ? 10 : 0;
        #pragma unroll
        for (int i = 0; i < 10; i++) red[warp][vb + i] = acc[i];
    }
    __syncthreads();

    __shared__ float z_sh[BS][CC];
    __shared__ float A_sh[BS][MM][CC];
    __shared__ float AM_sh[BS][MM][CC];

    if (t < BS * CC) {
        float zz = bvec[t % CC];
        #pragma unroll
        for (int w = 0; w < 8; w++) zz += red[w][t];
        z_sh[t / CC][t % CC] = zz;
    }

    // wait for gram blocks (typically long done)
    if (t == 0) {
        volatile unsigned int* p = &g_gram_cnt;
        while (*p < GRAM_BLKS) { __nanosleep(32); }
    }
    __syncthreads();
    __threadfence();   // acquire g_M writes

    if (warp < BS && b0 + warp < B) {
        const int smp = warp;
        float z[CC];
        #pragma unroll
        for (int l = 0; l < CC; l++) z[l] = z_sh[smp][l];
        float mz = z[0];
        #pragma unroll
        for (int l = 1; l < CC; l++) mz = fmaxf(mz, z[l]);
        float e[CC], se = 0.f;
        #pragma unroll
        for (int l = 0; l < CC; l++) { e[l] = __expf(z[l] - mz); se += e[l]; }
        float inv = 1.f / se;
        float s_[CC], r[CC];
        #pragma unroll
        for (int l = 0; l < CC; l++) {
            s_[l] = e[l] * inv;
            r[l]  = sqrtf(fmaf(s_[l], SCALE, NSTAB));
        }
        float u = 1.f - r[MM];

        float sumr = 0.f;
        #pragma unroll
        for (int l = 0; l < CC; l++) sumr += r[l];
        float arg = fminf(fmaxf(sumr * 0.31622776601683794f, -1.f), 1.f);
        float delta  = 2.f * acosf(arg);
        float factor = delta * delta / (4.f * u * u) * EPS2_INV;

        if (lane < MM) {
            int k = lane;
            float g1 = SCALE * s_[k] / (r[k] * u);
            float g2 = SCALE * r[k] * s_[MM] / (r[MM] * u * u);
            float gs = g1 + g2;
            #pragma unroll
            for (int l = 0; l < CC; l++) {
                float A = -s_[l] * gs;
                if (l == k)  A += g1;
                if (l == MM) A += g2;
                A_sh[smp][k][l] = A;
            }
        }
        __syncwarp();
        if (lane < MM) {
            #pragma unroll
            for (int lp = 0; lp < CC; lp++) {
                float v = 0.f;
                #pragma unroll
                for (int l = 0; l < CC; l++)
                    v = fmaf(A_sh[smp][lane][l], __ldcg(&g_M[l * CC + lp]), v);
                AM_sh[smp][lane][lp] = v;
            }
        }
        __syncwarp();

        float ss = 0.f;
        for (int idx = lane; idx < MM * MM; idx += 32) {
            int i = idx / MM, j = idx - i * MM;
            float g = 0.f;
            #pragma unroll
            for (int l = 0; l < CC; l++)
                g = fmaf(AM_sh[smp][i][l], A_sh[smp][j][l], g);
            if (i == j) g -= factor;
            ss = fmaf(g, g, ss);
        }
        #pragma unroll
        for (int o = 16; o; o >>= 1) ss += __shfl_xor_sync(0xffffffffu, ss, o);
        if (lane == 0)
            g_reg[b0 + smp] = sqrtf(ss) * (1.0f / (float)NN);
    }
    __syncthreads();

    // --- fused finalize: last main block reduces g_reg deterministically ---
    __shared__ unsigned int isLast;
    if (t == 0) {
        __threadfence();
        isLast = (atomicAdd(&g_fin_cnt, 1u) == (unsigned)mainBlocks - 1u);
    }
    __syncthreads();
    if (isLast) {
        __threadfence();
        __shared__ float fred[8];
        float s = 0.f;
        for (int i = t; i < B; i += 256) s += __ldcg(&g_reg[i]);
        #pragma unroll
        for (int o = 16; o; o >>= 1) s += __shfl_xor_sync(0xffffffffu, s, o);
        if ((t & 31) == 0) fred[t >> 5] = s;
        __syncthreads();
        if (t == 0) {
            float tot = 0.f;
            #pragma unroll
            for (int w = 0; w < 8; w++) tot += fred[w];
            out[0] = tot / (float)B;
            g_wt_cnt = 0;                // reset all counters for next replay
            g_gram_cnt = 0;
            g_fin_cnt = 0;
        }
        for (int i = 1 + t; i < out_size; i += 256) out[i] = 0.0f;
    }
}

// ---------------------------------------------------------------------------
extern "C" void kernel_launch(void* const* d_in, const int* in_sizes, int n_in,
                              void* d_out, int out_size) {
    const float* data = (const float*)d_in[0];   // [B, 3, 32, 32]
    const float* W    = (const float*)d_in[1];   // [3072, 10]
    const float* bvec = (const float*)d_in[2];   // [10]
    float* out = (float*)d_out;

    int B = in_sizes[0] / NN;
    if (B > MAX_B) B = MAX_B;
    int mainBlocks = (B + BS - 1) / BS;

    isometry_all<<<AUX_BLKS + mainBlocks, 256>>>(data, W, bvec, out,
                                                 out_size, B, mainBlocks);
}